// round 1
// baseline (speedup 1.0000x reference)
#include <cuda_runtime.h>
#include <math_constants.h>

#define NP 100000          // nodes per type (N_P == N_A)
#define EDGES 500000
#define HD 128             // H*D
#define NH 4               // heads

// ---------------- scratch (device globals; no allocation allowed) ------------
__device__ float g_Whp  [(size_t)NP*HD];
__device__ float g_Wha  [(size_t)NP*HD];
__device__ float g_Whp2p[(size_t)NP*HD];
__device__ float g_Whp2a[(size_t)NP*HD];
__device__ float g_Wha2p[(size_t)NP*HD];
__device__ float g_Wha2a[(size_t)NP*HD];
__device__ float g_es[4*(size_t)NP*NH];   // per-relation src-node attn dots
__device__ float g_ed[4*(size_t)NP*NH];   // per-relation dst-node attn dots
__device__ float g_m [4*(size_t)NP*NH];   // segment max
__device__ float g_s [4*(size_t)NP*NH];   // segment sum
__device__ float g_e [4*(size_t)EDGES*NH];// per-edge logits, then exp values

// ---------------- helpers ----------------------------------------------------
__device__ __forceinline__ float leaky(float x) {
    return x > 0.f ? x : 0.2f * x;
}

__device__ __forceinline__ void atomicMaxF(float* addr, float v) {
    // works for mixed signs given init = -inf (0xFF800000)
    if (v >= 0.f) atomicMax((int*)addr, __float_as_int(v));
    else          atomicMin((unsigned int*)addr, __float_as_uint(v));
}

// ---------------- init: m = -inf, s = 0 --------------------------------------
__global__ void init_ms() {
    int i = blockIdx.x * blockDim.x + threadIdx.x;
    if (i < NP * NH) {
        #pragma unroll
        for (int r = 0; r < 4; r++) {
            g_m[(size_t)r * NP * NH + i] = -CUDART_INF_F;
            g_s[(size_t)r * NP * NH + i] = 0.f;
        }
    }
}

// ---------------- fused GEMM: Wh = X@W + b, plus attn-dot epilogue -----------
// Block: 256 threads, tile = 64 rows x 128 cols. Thread tile: 8 rows x 4 cols.
// Dynamic smem: W [128x128] (64KB) + X tile [64x128] (32KB) = 96KB.
__global__ void gemm_fused(const float* __restrict__ X, const float* __restrict__ W,
                           const float* __restrict__ B, int M,
                           float* __restrict__ Wh, float* __restrict__ acc2,
                           const float* __restrict__ att_s, float* __restrict__ es,
                           const float* __restrict__ att_d1, float* __restrict__ ed1,
                           const float* __restrict__ att_d2, float* __restrict__ ed2)
{
    extern __shared__ float sm[];
    float* Ws = sm;              // 128*128
    float* Xs = sm + 128 * 128;  // 64*128
    const int tid = threadIdx.x;
    const int row0 = blockIdx.x * 64;

    {   // load W (16384 floats = 4096 float4)
        const float4* W4 = (const float4*)W;
        float4* Ws4 = (float4*)Ws;
        #pragma unroll
        for (int i = 0; i < 16; i++) Ws4[tid + i * 256] = W4[tid + i * 256];
    }
    {   // load X tile (2048 float4), zero-pad past M
        const float4* X4 = (const float4*)X;
        float4* Xs4 = (float4*)Xs;
        #pragma unroll
        for (int i = 0; i < 8; i++) {
            int idx = tid + i * 256;
            int r = idx >> 5;
            int gr = row0 + r;
            Xs4[idx] = (gr < M) ? X4[(size_t)gr * 32 + (idx & 31)]
                                : make_float4(0.f, 0.f, 0.f, 0.f);
        }
    }
    __syncthreads();

    const int tc = tid & 31;   // output col group (4 cols)
    const int tr = tid >> 5;   // row group (8 rows); == warp id
    float a0[8], a1[8], a2[8], a3[8];
    #pragma unroll
    for (int r = 0; r < 8; r++) { a0[r] = a1[r] = a2[r] = a3[r] = 0.f; }

    const float* xb = Xs + tr * 8 * 128;
    #pragma unroll 4
    for (int k4 = 0; k4 < 32; k4++) {
        const float* wr = Ws + (k4 * 4) * 128 + tc * 4;
        float4 w0 = *(const float4*)(wr);
        float4 w1 = *(const float4*)(wr + 128);
        float4 w2 = *(const float4*)(wr + 256);
        float4 w3 = *(const float4*)(wr + 384);
        #pragma unroll
        for (int r = 0; r < 8; r++) {
            float4 xv = *(const float4*)(xb + r * 128 + k4 * 4);
            a0[r] = fmaf(xv.x, w0.x, a0[r]); a1[r] = fmaf(xv.x, w0.y, a1[r]);
            a2[r] = fmaf(xv.x, w0.z, a2[r]); a3[r] = fmaf(xv.x, w0.w, a3[r]);
            a0[r] = fmaf(xv.y, w1.x, a0[r]); a1[r] = fmaf(xv.y, w1.y, a1[r]);
            a2[r] = fmaf(xv.y, w1.z, a2[r]); a3[r] = fmaf(xv.y, w1.w, a3[r]);
            a0[r] = fmaf(xv.z, w2.x, a0[r]); a1[r] = fmaf(xv.z, w2.y, a1[r]);
            a2[r] = fmaf(xv.z, w2.z, a2[r]); a3[r] = fmaf(xv.z, w2.w, a3[r]);
            a0[r] = fmaf(xv.w, w3.x, a0[r]); a1[r] = fmaf(xv.w, w3.y, a1[r]);
            a2[r] = fmaf(xv.w, w3.z, a2[r]); a3[r] = fmaf(xv.w, w3.w, a3[r]);
        }
    }

    float4 bv = *(const float4*)(B + tc * 4);
    float4 asv = make_float4(0.f,0.f,0.f,0.f), ad1 = asv, ad2 = asv;
    if (att_s)  asv = *(const float4*)(att_s  + tc * 4);
    if (att_d1) ad1 = *(const float4*)(att_d1 + tc * 4);
    if (att_d2) ad2 = *(const float4*)(att_d2 + tc * 4);
    const int head = tc >> 3;   // 4 cols per thread, 32 cols per head

    #pragma unroll
    for (int r = 0; r < 8; r++) {
        int gr = row0 + tr * 8 + r;
        float y0 = a0[r] + bv.x, y1 = a1[r] + bv.y;
        float y2 = a2[r] + bv.z, y3 = a3[r] + bv.w;
        bool ok = (gr < M);
        if (ok) {
            float4 yv = make_float4(y0, y1, y2, y3);
            *(float4*)(Wh + (size_t)gr * HD + tc * 4) = yv;
            if (acc2) *(float4*)(acc2 + (size_t)gr * HD + tc * 4) = yv;
        }
        // attention dot partials: att[H,D] flattens to exactly the col index
        float ps = y0*asv.x + y1*asv.y + y2*asv.z + y3*asv.w;
        float p1 = y0*ad1.x + y1*ad1.y + y2*ad1.z + y3*ad1.w;
        float p2 = y0*ad2.x + y1*ad2.y + y2*ad2.z + y3*ad2.w;
        ps += __shfl_down_sync(0xffffffffu, ps, 4, 8);
        ps += __shfl_down_sync(0xffffffffu, ps, 2, 8);
        ps += __shfl_down_sync(0xffffffffu, ps, 1, 8);
        p1 += __shfl_down_sync(0xffffffffu, p1, 4, 8);
        p1 += __shfl_down_sync(0xffffffffu, p1, 2, 8);
        p1 += __shfl_down_sync(0xffffffffu, p1, 1, 8);
        p2 += __shfl_down_sync(0xffffffffu, p2, 4, 8);
        p2 += __shfl_down_sync(0xffffffffu, p2, 2, 8);
        p2 += __shfl_down_sync(0xffffffffu, p2, 1, 8);
        if (((tc & 7) == 0) && ok) {
            if (es)  es [(size_t)gr * NH + head] = ps;
            if (ed1) ed1[(size_t)gr * NH + head] = p1;
            if (ed2) ed2[(size_t)gr * NH + head] = p2;
        }
    }
}

// ---------------- edge pass A: e = leaky(es[src]+ed[dst]); segment max -------
__global__ void edge_pass_a(const int* __restrict__ src, const int* __restrict__ dst,
                            const float* __restrict__ es, const float* __restrict__ ed,
                            float* __restrict__ ebuf, float* __restrict__ m)
{
    int i = blockIdx.x * blockDim.x + threadIdx.x;
    if (i >= EDGES) return;
    int s = src[i], d = dst[i];
    float4 a = *(const float4*)(es + (size_t)s * 4);
    float4 b = *(const float4*)(ed + (size_t)d * 4);
    float e0 = leaky(a.x + b.x), e1 = leaky(a.y + b.y);
    float e2 = leaky(a.z + b.z), e3 = leaky(a.w + b.w);
    *(float4*)(ebuf + (size_t)i * 4) = make_float4(e0, e1, e2, e3);
    float* mp = m + (size_t)d * 4;
    atomicMaxF(mp + 0, e0);
    atomicMaxF(mp + 1, e1);
    atomicMaxF(mp + 2, e2);
    atomicMaxF(mp + 3, e3);
}

// ---------------- edge pass B: ee = exp(e - m[dst]); segment sum -------------
__global__ void edge_pass_b(const int* __restrict__ dst,
                            float* __restrict__ ebuf, const float* __restrict__ m,
                            float* __restrict__ ssum)
{
    int i = blockIdx.x * blockDim.x + threadIdx.x;
    if (i >= EDGES) return;
    int d = dst[i];
    float4 e  = *(const float4*)(ebuf + (size_t)i * 4);
    float4 mv = *(const float4*)(m + (size_t)d * 4);
    float e0 = __expf(e.x - mv.x), e1 = __expf(e.y - mv.y);
    float e2 = __expf(e.z - mv.z), e3 = __expf(e.w - mv.w);
    *(float4*)(ebuf + (size_t)i * 4) = make_float4(e0, e1, e2, e3);
    float* sp = ssum + (size_t)d * 4;
    atomicAdd(sp + 0, e0);
    atomicAdd(sp + 1, e1);
    atomicAdd(sp + 2, e2);
    atomicAdd(sp + 3, e3);
}

// ---------------- edge pass C: scatter Wh_src[src] * (ee/s[dst]) -------------
// One warp per edge; lane l owns 4 floats at col l*4 (head = l>>3).
__global__ void edge_pass_c(const int* __restrict__ src, const int* __restrict__ dst,
                            const float* __restrict__ ebuf, const float* __restrict__ ssum,
                            const float* __restrict__ WhS, float* __restrict__ acc)
{
    int gt = blockIdx.x * blockDim.x + threadIdx.x;
    int w = gt >> 5;
    if (w >= EDGES) return;
    int lane = gt & 31;
    int s = src[w], d = dst[w];
    int h = lane >> 3;
    float a = ebuf[(size_t)w * 4 + h] / ssum[(size_t)d * 4 + h];
    float4 v = *(const float4*)(WhS + (size_t)s * HD + lane * 4);
    float* o = acc + (size_t)d * HD + lane * 4;
    atomicAdd(o + 0, v.x * a);
    atomicAdd(o + 1, v.y * a);
    atomicAdd(o + 2, v.z * a);
    atomicAdd(o + 3, v.w * a);
}

// ---------------- final ReLU in place on d_out -------------------------------
__global__ void relu_k(float4* __restrict__ out, int n4)
{
    int i = blockIdx.x * blockDim.x + threadIdx.x;
    if (i < n4) {
        float4 v = out[i];
        v.x = fmaxf(v.x, 0.f); v.y = fmaxf(v.y, 0.f);
        v.z = fmaxf(v.z, 0.f); v.w = fmaxf(v.w, 0.f);
        out[i] = v;
    }
}

// -----------------------------------------------------------------------------
extern "C" void kernel_launch(void* const* d_in, const int* in_sizes, int n_in,
                              void* d_out, int out_size)
{
    const float* feat_P = (const float*)d_in[0];
    const float* feat_A = (const float*)d_in[1];
    const int* src[4] = { (const int*)d_in[2], (const int*)d_in[4],
                          (const int*)d_in[6], (const int*)d_in[8] };
    const int* dst[4] = { (const int*)d_in[3], (const int*)d_in[5],
                          (const int*)d_in[7], (const int*)d_in[9] };
    const float* W_P   = (const float*)d_in[10]; const float* b_P   = (const float*)d_in[11];
    const float* W_A   = (const float*)d_in[12]; const float* b_A   = (const float*)d_in[13];
    const float* W_p2p = (const float*)d_in[14]; const float* b_p2p = (const float*)d_in[15];
    const float* W_p2a = (const float*)d_in[16]; const float* b_p2a = (const float*)d_in[17];
    const float* W_a2p = (const float*)d_in[18]; const float* b_a2p = (const float*)d_in[19];
    const float* W_a2a = (const float*)d_in[20]; const float* b_a2a = (const float*)d_in[21];
    const float* att_src[4] = { (const float*)d_in[22], (const float*)d_in[24],
                                (const float*)d_in[26], (const float*)d_in[28] };
    const float* att_dst[4] = { (const float*)d_in[23], (const float*)d_in[25],
                                (const float*)d_in[27], (const float*)d_in[29] };

    float* out  = (float*)d_out;
    float* outP = out;
    float* outA = out + (size_t)NP * HD;

    float *whp, *wha, *whp2p, *whp2a, *wha2p, *wha2a, *esb, *edb, *mb, *sb, *eb;
    cudaGetSymbolAddress((void**)&whp,   g_Whp);
    cudaGetSymbolAddress((void**)&wha,   g_Wha);
    cudaGetSymbolAddress((void**)&whp2p, g_Whp2p);
    cudaGetSymbolAddress((void**)&whp2a, g_Whp2a);
    cudaGetSymbolAddress((void**)&wha2p, g_Wha2p);
    cudaGetSymbolAddress((void**)&wha2a, g_Wha2a);
    cudaGetSymbolAddress((void**)&esb,   g_es);
    cudaGetSymbolAddress((void**)&edb,   g_ed);
    cudaGetSymbolAddress((void**)&mb,    g_m);
    cudaGetSymbolAddress((void**)&sb,    g_s);
    cudaGetSymbolAddress((void**)&eb,    g_e);

    const size_t SMEM = 96 * 1024;
    cudaFuncSetAttribute(gemm_fused, cudaFuncAttributeMaxDynamicSharedMemorySize, (int)SMEM);

    // init segment max/sum scratch
    init_ms<<<(NP * NH + 255) / 256, 256>>>();

    const int GB = (NP + 63) / 64;
    const size_t T = (size_t)NP * NH;

    // self transforms (also seed d_out accumulators) + dst attn dots
    gemm_fused<<<GB, 256, SMEM>>>(feat_P, W_P, b_P, NP, whp, outP,
                                  nullptr, nullptr,
                                  att_dst[0], edb + 0 * T,   // ed_p2p (dst = P)
                                  att_dst[2], edb + 2 * T);  // ed_a2p (dst = P)
    gemm_fused<<<GB, 256, SMEM>>>(feat_A, W_A, b_A, NP, wha, outA,
                                  nullptr, nullptr,
                                  att_dst[1], edb + 1 * T,   // ed_p2a (dst = A)
                                  att_dst[3], edb + 3 * T);  // ed_a2a (dst = A)
    // relation transforms + src attn dots
    gemm_fused<<<GB, 256, SMEM>>>(feat_P, W_p2p, b_p2p, NP, whp2p, nullptr,
                                  att_src[0], esb + 0 * T,
                                  nullptr, nullptr, nullptr, nullptr);
    gemm_fused<<<GB, 256, SMEM>>>(feat_P, W_p2a, b_p2a, NP, whp2a, nullptr,
                                  att_src[1], esb + 1 * T,
                                  nullptr, nullptr, nullptr, nullptr);
    gemm_fused<<<GB, 256, SMEM>>>(feat_A, W_a2p, b_a2p, NP, wha2p, nullptr,
                                  att_src[2], esb + 2 * T,
                                  nullptr, nullptr, nullptr, nullptr);
    gemm_fused<<<GB, 256, SMEM>>>(feat_A, W_a2a, b_a2a, NP, wha2a, nullptr,
                                  att_src[3], esb + 3 * T,
                                  nullptr, nullptr, nullptr, nullptr);

    float* whsrc[4] = { whp2p, whp2a, wha2p, wha2a };
    float* accs[4]  = { outP,  outA,  outP,  outA  };

    const int EB1 = (EDGES + 255) / 256;              // 1 thread / edge
    const int EBW = ((size_t)EDGES * 32 + 255) / 256; // 1 warp / edge
    for (int r = 0; r < 4; r++) {
        float* er = eb + (size_t)r * EDGES * NH;
        edge_pass_a<<<EB1, 256>>>(src[r], dst[r], esb + r * T, edb + r * T,
                                  er, mb + r * T);
        edge_pass_b<<<EB1, 256>>>(dst[r], er, mb + r * T, sb + r * T);
        edge_pass_c<<<EBW, 256>>>(src[r], dst[r], er, sb + r * T,
                                  whsrc[r], accs[r]);
    }

    const int n4 = 2 * NP * HD / 4;
    relu_k<<<(n4 + 255) / 256, 256>>>((float4*)out, n4);
}

// round 3
// speedup vs baseline: 1.8844x; 1.8844x over previous
#include <cuda_runtime.h>
#include <math_constants.h>

#define NP 100000          // nodes per type (N_P == N_A)
#define EDGES 500000
#define HD 128             // H*D
#define NH 4               // heads
#define PAD 132            // smem row stride (floats) to kill bank conflicts

// ---------------- scratch (device globals; no allocation allowed) ------------
__device__ float g_Whp  [(size_t)NP*HD];
__device__ float g_Wha  [(size_t)NP*HD];
__device__ float g_Whp2p[(size_t)NP*HD];
__device__ float g_Whp2a[(size_t)NP*HD];
__device__ float g_Wha2p[(size_t)NP*HD];
__device__ float g_Wha2a[(size_t)NP*HD];
__device__ float g_es[4*(size_t)NP*NH];   // per-relation src-node attn dots
__device__ float g_ed[4*(size_t)NP*NH];   // per-relation dst-node attn dots
__device__ float g_s [4*(size_t)NP*NH];   // segment sum of exp(e) -> 1/s
__device__ float g_e [4*(size_t)EDGES*NH];// per-edge exp(e)

// ---------------- helpers ----------------------------------------------------
__device__ __forceinline__ float leaky(float x) {
    return x > 0.f ? x : 0.2f * x;
}

__device__ __forceinline__ unsigned f2tf32(float f) {
    unsigned u;
    asm("cvt.rna.tf32.f32 %0, %1;" : "=r"(u) : "f"(f));
    return u;
}

__device__ __forceinline__ void redAddV4(float* p, float a, float b, float c, float d) {
    asm volatile("red.global.add.v4.f32 [%0], {%1,%2,%3,%4};"
                 :: "l"(p), "f"(a), "f"(b), "f"(c), "f"(d) : "memory");
}

__device__ __forceinline__ void mma_tf32(float d[4], const unsigned a[4],
                                         unsigned b0, unsigned b1) {
    asm volatile(
        "mma.sync.aligned.m16n8k8.row.col.f32.tf32.tf32.f32 "
        "{%0,%1,%2,%3}, {%4,%5,%6,%7}, {%8,%9}, {%0,%1,%2,%3};"
        : "+f"(d[0]), "+f"(d[1]), "+f"(d[2]), "+f"(d[3])
        : "r"(a[0]), "r"(a[1]), "r"(a[2]), "r"(a[3]), "r"(b0), "r"(b1));
}

// ---------------- init: s = 0 ------------------------------------------------
__global__ void init_s() {
    int i = blockIdx.x * blockDim.x + threadIdx.x;
    if (i < 4 * NP * NH) g_s[i] = 0.f;
}

// ---------------- invert segment sums in place: s -> 1/s ---------------------
__global__ void inv_s() {
    int i = blockIdx.x * blockDim.x + threadIdx.x;
    if (i < 4 * NP * NH) {
        float v = g_s[i];
        g_s[i] = (v != 0.f) ? __frcp_rn(v) : 0.f;
    }
}

// ---------------- tensor-core GEMM: Wh = X@W + b, fused attn-dot epilogue ----
// Block 256 thr = 8 warps (4 in M x 2 in N). Block tile 128x128. K=128 resident.
// Dyn smem: A[128][PAD] + W[128][PAD] floats (tf32 bit patterns) = 135168 B.
__global__ void gemm_tc(const float* __restrict__ X, const float* __restrict__ W,
                        const float* __restrict__ Bv, int M,
                        float* __restrict__ Wh, float* __restrict__ acc2,
                        const float* __restrict__ att1, float* __restrict__ o1,
                        const float* __restrict__ att2, float* __restrict__ o2)
{
    extern __shared__ float sm[];
    float* As = sm;               // 128 x PAD
    float* Ws = sm + 128 * PAD;   // 128 x PAD
    const int tid  = threadIdx.x;
    const int row0 = blockIdx.x * 128;

    // load W [128][128] -> tf32 into padded smem
    #pragma unroll
    for (int i = 0; i < 16; i++) {
        int idx = tid + i * 256;            // float4 index (4096 total)
        int r = idx >> 5, c4 = idx & 31;
        float4 v = ((const float4*)W)[idx];
        float* d = Ws + r * PAD + c4 * 4;
        ((unsigned*)d)[0] = f2tf32(v.x);
        ((unsigned*)d)[1] = f2tf32(v.y);
        ((unsigned*)d)[2] = f2tf32(v.z);
        ((unsigned*)d)[3] = f2tf32(v.w);
    }
    // load X tile [128][128] -> tf32, zero-pad past M
    #pragma unroll
    for (int i = 0; i < 16; i++) {
        int idx = tid + i * 256;
        int r = idx >> 5, c4 = idx & 31;
        int gr = row0 + r;
        float4 v = (gr < M) ? ((const float4*)X)[(size_t)gr * 32 + c4]
                            : make_float4(0.f, 0.f, 0.f, 0.f);
        float* d = As + r * PAD + c4 * 4;
        ((unsigned*)d)[0] = f2tf32(v.x);
        ((unsigned*)d)[1] = f2tf32(v.y);
        ((unsigned*)d)[2] = f2tf32(v.z);
        ((unsigned*)d)[3] = f2tf32(v.w);
    }
    __syncthreads();

    const int wid   = tid >> 5;
    const int lane  = tid & 31;
    const int warpM = wid & 3;        // 4 warps in M
    const int warpN = wid >> 2;       // 2 warps in N
    const int wm    = warpM * 32;
    const int wn    = warpN * 64;
    const int g     = lane >> 2;      // group id 0..7
    const int tig   = lane & 3;       // thread-in-group

    float acc[2][8][4];
    #pragma unroll
    for (int mi = 0; mi < 2; mi++)
        #pragma unroll
        for (int ni = 0; ni < 8; ni++)
            #pragma unroll
            for (int j = 0; j < 4; j++) acc[mi][ni][j] = 0.f;

    const unsigned* Au = (const unsigned*)As;
    const unsigned* Wu = (const unsigned*)Ws;

    #pragma unroll
    for (int kk = 0; kk < 16; kk++) {
        const int k0 = kk * 8;
        unsigned a[2][4];
        #pragma unroll
        for (int mi = 0; mi < 2; mi++) {
            int rb = wm + mi * 16;
            a[mi][0] = Au[(rb + g    ) * PAD + k0 + tig];
            a[mi][1] = Au[(rb + g + 8) * PAD + k0 + tig];
            a[mi][2] = Au[(rb + g    ) * PAD + k0 + tig + 4];
            a[mi][3] = Au[(rb + g + 8) * PAD + k0 + tig + 4];
        }
        #pragma unroll
        for (int ni = 0; ni < 8; ni++) {
            unsigned b0 = Wu[(k0 + tig    ) * PAD + wn + ni * 8 + g];
            unsigned b1 = Wu[(k0 + tig + 4) * PAD + wn + ni * 8 + g];
            mma_tf32(acc[0][ni], a[0], b0, b1);
            mma_tf32(acc[1][ni], a[1], b0, b1);
        }
    }

    // epilogue: bias, store Wh (+acc2), fused attention dot products
    // thread covers cols wn + ni*8 + 2*tig (+1); rows row0+wm+mi*16+g (+8)
    float pa[2][2][2][2]; // [vec][mi][half][head_local]
    #pragma unroll
    for (int v = 0; v < 2; v++)
        #pragma unroll
        for (int mi = 0; mi < 2; mi++)
            #pragma unroll
            for (int hf = 0; hf < 2; hf++)
                #pragma unroll
                for (int hl = 0; hl < 2; hl++) pa[v][mi][hf][hl] = 0.f;

    #pragma unroll
    for (int ni = 0; ni < 8; ni++) {
        const int c0 = wn + ni * 8 + 2 * tig;
        const int hl = ni >> 2;       // head-local within warp (0/1)
        const float b0 = __ldg(Bv + c0), b1 = __ldg(Bv + c0 + 1);
        float a10 = 0.f, a11 = 0.f, a20 = 0.f, a21 = 0.f;
        if (att1) { a10 = __ldg(att1 + c0); a11 = __ldg(att1 + c0 + 1); }
        if (att2) { a20 = __ldg(att2 + c0); a21 = __ldg(att2 + c0 + 1); }
        #pragma unroll
        for (int mi = 0; mi < 2; mi++) {
            int r0 = row0 + wm + mi * 16 + g;
            float y00 = acc[mi][ni][0] + b0, y01 = acc[mi][ni][1] + b1; // row r0
            float y10 = acc[mi][ni][2] + b0, y11 = acc[mi][ni][3] + b1; // row r0+8
            if (r0 < M) {
                *(float2*)(Wh + (size_t)r0 * HD + c0) = make_float2(y00, y01);
                if (acc2) *(float2*)(acc2 + (size_t)r0 * HD + c0) = make_float2(y00, y01);
            }
            if (r0 + 8 < M) {
                *(float2*)(Wh + (size_t)(r0 + 8) * HD + c0) = make_float2(y10, y11);
                if (acc2) *(float2*)(acc2 + (size_t)(r0 + 8) * HD + c0) = make_float2(y10, y11);
            }
            pa[0][mi][0][hl] += y00 * a10 + y01 * a11;
            pa[0][mi][1][hl] += y10 * a10 + y11 * a11;
            pa[1][mi][0][hl] += y00 * a20 + y01 * a21;
            pa[1][mi][1][hl] += y10 * a20 + y11 * a21;
        }
    }

    // reduce over the 4 threads of each row-group (tig), then write
    #pragma unroll
    for (int v = 0; v < 2; v++) {
        float* o = (v == 0) ? o1 : o2;
        if (!o) continue;
        #pragma unroll
        for (int mi = 0; mi < 2; mi++)
            #pragma unroll
            for (int hf = 0; hf < 2; hf++)
                #pragma unroll
                for (int hl = 0; hl < 2; hl++) {
                    float p = pa[v][mi][hf][hl];
                    p += __shfl_down_sync(0xffffffffu, p, 2, 4);
                    p += __shfl_down_sync(0xffffffffu, p, 1, 4);
                    if (tig == 0) {
                        int r = row0 + wm + mi * 16 + hf * 8 + g;
                        if (r < M) o[(size_t)r * NH + warpN * 2 + hl] = p;
                    }
                }
    }
}

// ---------------- edge pass AB: ee = exp(leaky(es[src]+ed[dst])); seg-sum ----
// Softmax shift is skipped: logits are O(5) so exp never overflows, and
// exp(e)/sum(exp(e)) is shift-invariant -> identical result.
__global__ void edge_ab(const int* __restrict__ src, const int* __restrict__ dst,
                        const float* __restrict__ es, const float* __restrict__ ed,
                        float* __restrict__ ebuf, float* __restrict__ ssum)
{
    int i = blockIdx.x * blockDim.x + threadIdx.x;
    if (i >= EDGES) return;
    int s = src[i], d = dst[i];
    float4 a = *(const float4*)(es + (size_t)s * 4);
    float4 b = *(const float4*)(ed + (size_t)d * 4);
    float e0 = __expf(leaky(a.x + b.x));
    float e1 = __expf(leaky(a.y + b.y));
    float e2 = __expf(leaky(a.z + b.z));
    float e3 = __expf(leaky(a.w + b.w));
    *(float4*)(ebuf + (size_t)i * 4) = make_float4(e0, e1, e2, e3);
    redAddV4(ssum + (size_t)d * 4, e0, e1, e2, e3);
}

// ---------------- edge pass C: scatter Wh_src[src] * (ee * inv_s[dst]) -------
// One warp per edge; lane l owns 4 floats at col l*4 (head = l>>3).
__global__ void edge_c(const int* __restrict__ src, const int* __restrict__ dst,
                       const float* __restrict__ ebuf, const float* __restrict__ sinv,
                       const float* __restrict__ WhS, float* __restrict__ acc)
{
    int gt = blockIdx.x * blockDim.x + threadIdx.x;
    int w = gt >> 5;
    if (w >= EDGES) return;
    int lane = gt & 31;
    int s = src[w], d = dst[w];
    int h = lane >> 3;
    float a = ebuf[(size_t)w * 4 + h] * sinv[(size_t)d * 4 + h];
    float4 v = *(const float4*)(WhS + (size_t)s * HD + lane * 4);
    redAddV4(acc + (size_t)d * HD + lane * 4, v.x * a, v.y * a, v.z * a, v.w * a);
}

// ---------------- final ReLU in place on d_out -------------------------------
__global__ void relu_k(float4* __restrict__ out, int n4)
{
    int i = blockIdx.x * blockDim.x + threadIdx.x;
    if (i < n4) {
        float4 v = out[i];
        v.x = fmaxf(v.x, 0.f); v.y = fmaxf(v.y, 0.f);
        v.z = fmaxf(v.z, 0.f); v.w = fmaxf(v.w, 0.f);
        out[i] = v;
    }
}

// -----------------------------------------------------------------------------
extern "C" void kernel_launch(void* const* d_in, const int* in_sizes, int n_in,
                              void* d_out, int out_size)
{
    const float* feat_P = (const float*)d_in[0];
    const float* feat_A = (const float*)d_in[1];
    const int* src[4] = { (const int*)d_in[2], (const int*)d_in[4],
                          (const int*)d_in[6], (const int*)d_in[8] };
    const int* dst[4] = { (const int*)d_in[3], (const int*)d_in[5],
                          (const int*)d_in[7], (const int*)d_in[9] };
    const float* W_P   = (const float*)d_in[10]; const float* b_P   = (const float*)d_in[11];
    const float* W_A   = (const float*)d_in[12]; const float* b_A   = (const float*)d_in[13];
    const float* W_p2p = (const float*)d_in[14]; const float* b_p2p = (const float*)d_in[15];
    const float* W_p2a = (const float*)d_in[16]; const float* b_p2a = (const float*)d_in[17];
    const float* W_a2p = (const float*)d_in[18]; const float* b_a2p = (const float*)d_in[19];
    const float* W_a2a = (const float*)d_in[20]; const float* b_a2a = (const float*)d_in[21];
    const float* att_src[4] = { (const float*)d_in[22], (const float*)d_in[24],
                                (const float*)d_in[26], (const float*)d_in[28] };
    const float* att_dst[4] = { (const float*)d_in[23], (const float*)d_in[25],
                                (const float*)d_in[27], (const float*)d_in[29] };

    float* out  = (float*)d_out;
    float* outP = out;
    float* outA = out + (size_t)NP * HD;

    float *whp, *wha, *whp2p, *whp2a, *wha2p, *wha2a, *esb, *edb, *sb, *eb;
    cudaGetSymbolAddress((void**)&whp,   g_Whp);
    cudaGetSymbolAddress((void**)&wha,   g_Wha);
    cudaGetSymbolAddress((void**)&whp2p, g_Whp2p);
    cudaGetSymbolAddress((void**)&whp2a, g_Whp2a);
    cudaGetSymbolAddress((void**)&wha2p, g_Wha2p);
    cudaGetSymbolAddress((void**)&wha2a, g_Wha2a);
    cudaGetSymbolAddress((void**)&esb,   g_es);
    cudaGetSymbolAddress((void**)&edb,   g_ed);
    cudaGetSymbolAddress((void**)&sb,    g_s);
    cudaGetSymbolAddress((void**)&eb,    g_e);

    const size_t SMEM = 2 * 128 * PAD * sizeof(float);   // 135168
    cudaFuncSetAttribute(gemm_tc, cudaFuncAttributeMaxDynamicSharedMemorySize, (int)SMEM);

    init_s<<<(4 * NP * NH + 255) / 256, 256>>>();

    const int GB = (NP + 127) / 128;
    const size_t T = (size_t)NP * NH;

    // self transforms (seed d_out) + dst attn dots
    gemm_tc<<<GB, 256, SMEM>>>(feat_P, W_P, b_P, NP, whp, outP,
                               att_dst[0], edb + 0 * T,   // ed_p2p (dst = P)
                               att_dst[2], edb + 2 * T);  // ed_a2p (dst = P)
    gemm_tc<<<GB, 256, SMEM>>>(feat_A, W_A, b_A, NP, wha, outA,
                               att_dst[1], edb + 1 * T,   // ed_p2a (dst = A)
                               att_dst[3], edb + 3 * T);  // ed_a2a (dst = A)
    // relation transforms + src attn dots
    gemm_tc<<<GB, 256, SMEM>>>(feat_P, W_p2p, b_p2p, NP, whp2p, nullptr,
                               att_src[0], esb + 0 * T, nullptr, nullptr);
    gemm_tc<<<GB, 256, SMEM>>>(feat_P, W_p2a, b_p2a, NP, whp2a, nullptr,
                               att_src[1], esb + 1 * T, nullptr, nullptr);
    gemm_tc<<<GB, 256, SMEM>>>(feat_A, W_a2p, b_a2p, NP, wha2p, nullptr,
                               att_src[2], esb + 2 * T, nullptr, nullptr);
    gemm_tc<<<GB, 256, SMEM>>>(feat_A, W_a2a, b_a2a, NP, wha2a, nullptr,
                               att_src[3], esb + 3 * T, nullptr, nullptr);

    float* whsrc[4] = { whp2p, whp2a, wha2p, wha2a };
    float* accs[4]  = { outP,  outA,  outP,  outA  };

    const int EB1 = (EDGES + 255) / 256;                      // 1 thread / edge
    const int EBW = (int)(((size_t)EDGES * 32 + 255) / 256);  // 1 warp / edge

    for (int r = 0; r < 4; r++)
        edge_ab<<<EB1, 256>>>(src[r], dst[r], esb + r * T, edb + r * T,
                              eb + (size_t)r * EDGES * NH, sb + r * T);

    inv_s<<<(4 * NP * NH + 255) / 256, 256>>>();

    for (int r = 0; r < 4; r++)
        edge_c<<<EBW, 256>>>(src[r], dst[r], eb + (size_t)r * EDGES * NH,
                             sb + r * T, whsrc[r], accs[r]);

    const int n4 = 2 * NP * HD / 4;
    relu_k<<<(n4 + 255) / 256, 256>>>((float4*)out, n4);
}